// round 1
// baseline (speedup 1.0000x reference)
#include <cuda_runtime.h>

#define BB 64
#define SS 2048
#define DD 512
#define UU 512

// Scratch (no allocations allowed)
__device__ float g_bias[BB * UU];     // dec@W2 + b1 + b2
__device__ float g_scores[BB * SS];   // pre-softmax scores

__device__ __forceinline__ float tanh_fast(float x) {
    // tanh(x) = 1 - 2/(exp(2x)+1); exact limits at +/-inf, abs err ~1e-7
    float e = __expf(2.0f * x);
    return 1.0f - 2.0f / (e + 1.0f);
}

// ---------------------------------------------------------------------------
// Kernel A: g_bias[b,u] = sum_k dec[b,k]*W2[k,u] + b1[u] + b2[u]
// ---------------------------------------------------------------------------
__global__ __launch_bounds__(512) void kernA(const float* __restrict__ dec,
                                             const float* __restrict__ W2,
                                             const float* __restrict__ b1,
                                             const float* __restrict__ b2) {
    __shared__ float ds[DD];
    int b = blockIdx.x;
    for (int i = threadIdx.x; i < DD; i += blockDim.x) ds[i] = dec[b * DD + i];
    __syncthreads();
    int u = threadIdx.x;  // blockDim = 512 = UU
    float acc = 0.0f;
#pragma unroll 8
    for (int k = 0; k < DD; k++) acc = fmaf(ds[k], W2[k * UU + u], acc);
    g_bias[b * UU + u] = acc + b1[u] + b2[u];
}

// ---------------------------------------------------------------------------
// Kernel B: fused  scores[b,s] = V . tanh(enc[b,s,:]@W1 + g_bias[b,:]) + bv
// 64-row tiles, full-K enc tile in smem, W1 double-buffered 32x64 tiles,
// 4x4 microtile per thread via packed fma.rn.f32x2.
// ---------------------------------------------------------------------------
#define ESTR 516                 // enc smem row stride (pad, mult of 4)
#define WSTR 68                  // W1 tile row stride
#define SMEM_FLOATS (64 * ESTR + 2 * 32 * WSTR + 512 + 512)

__global__ __launch_bounds__(256) void kernB(const float* __restrict__ enc,
                                             const float* __restrict__ W1,
                                             const float* __restrict__ V,
                                             const float* __restrict__ bvp) {
    extern __shared__ float sm[];
    float* encS = sm;                        // [64][ESTR]
    float* w1S  = sm + 64 * ESTR;            // [2][32][WSTR]
    float* gB   = w1S + 2 * 32 * WSTR;       // [512]
    float* Vs   = gB + 512;                  // [512]

    const int tid = threadIdx.x;
    const int tx  = tid & 15;                // col group 0..15
    const int ty  = tid >> 4;                // row group 0..15
    const int R   = blockIdx.x * 64;         // global flattened row base
    const int b   = R >> 11;                 // R / SS
    const int s0  = R & (SS - 1);
    const float bv0 = bvp[0];

    // Load enc tile [64][512] -> smem (coalesced float4, conflict-free stores)
    const float* erow = enc + (size_t)R * DD;
    for (int idx = tid; idx < 64 * 128; idx += 256) {
        int row = idx >> 7, kq = idx & 127;
        float4 v = *(const float4*)(erow + row * DD + kq * 4);
        *(float4*)(encS + row * ESTR + kq * 4) = v;
    }
    for (int i = tid; i < 512; i += 256) {
        gB[i] = g_bias[b * 512 + i];
        Vs[i] = V[i];
    }

    // Preload first W1 tile (tile index 0 -> nc=0, kt=0)
    float4 pre[2];
#pragma unroll
    for (int r = 0; r < 2; r++) {
        int idx = tid + r * 256;
        int kk = idx >> 4, nq = idx & 15;
        pre[r] = *(const float4*)(W1 + (size_t)kk * UU + nq * 4);
    }
    __syncthreads();
#pragma unroll
    for (int r = 0; r < 2; r++) {
        int idx = tid + r * 256;
        int kk = idx >> 4, nq = idx & 15;
        *(float4*)(w1S + kk * WSTR + nq * 4) = pre[r];
    }
    __syncthreads();

    float scp[4] = {0.f, 0.f, 0.f, 0.f};
    int buf = 0;

    for (int nc = 0; nc < 8; nc++) {
        unsigned long long acc[4][2];
#pragma unroll
        for (int i = 0; i < 4; i++) { acc[i][0] = 0ull; acc[i][1] = 0ull; }

        for (int kt = 0; kt < 16; kt++) {
            // Prefetch next W1 tile (global tile order: tnum = nc*16 + kt)
            int tnum = nc * 16 + kt + 1;
            bool more = (tnum < 128);
            if (more) {
                int nn = tnum >> 4, kn = tnum & 15;
#pragma unroll
                for (int r = 0; r < 2; r++) {
                    int idx = tid + r * 256;
                    int kk = idx >> 4, nq = idx & 15;
                    pre[r] = *(const float4*)(W1 + (size_t)(kn * 32 + kk) * UU +
                                              nn * 64 + nq * 4);
                }
            }

            const float* wb = w1S + buf * 32 * WSTR;
            const float* ea = encS + (ty * 4) * ESTR + kt * 32;
#pragma unroll
            for (int k = 0; k < 32; k++) {
                float a0 = ea[k];
                float a1 = ea[ESTR + k];
                float a2 = ea[2 * ESTR + k];
                float a3 = ea[3 * ESTR + k];
                float4 b4 = *(const float4*)(wb + k * WSTR + tx * 4);
                unsigned long long bx, by, av;
                asm("mov.b64 %0, {%1, %2};" : "=l"(bx) : "f"(b4.x), "f"(b4.y));
                asm("mov.b64 %0, {%1, %2};" : "=l"(by) : "f"(b4.z), "f"(b4.w));
                asm("mov.b64 %0, {%1, %2};" : "=l"(av) : "f"(a0), "f"(a0));
                asm("fma.rn.f32x2 %0, %1, %2, %0;" : "+l"(acc[0][0]) : "l"(av), "l"(bx));
                asm("fma.rn.f32x2 %0, %1, %2, %0;" : "+l"(acc[0][1]) : "l"(av), "l"(by));
                asm("mov.b64 %0, {%1, %2};" : "=l"(av) : "f"(a1), "f"(a1));
                asm("fma.rn.f32x2 %0, %1, %2, %0;" : "+l"(acc[1][0]) : "l"(av), "l"(bx));
                asm("fma.rn.f32x2 %0, %1, %2, %0;" : "+l"(acc[1][1]) : "l"(av), "l"(by));
                asm("mov.b64 %0, {%1, %2};" : "=l"(av) : "f"(a2), "f"(a2));
                asm("fma.rn.f32x2 %0, %1, %2, %0;" : "+l"(acc[2][0]) : "l"(av), "l"(bx));
                asm("fma.rn.f32x2 %0, %1, %2, %0;" : "+l"(acc[2][1]) : "l"(av), "l"(by));
                asm("mov.b64 %0, {%1, %2};" : "=l"(av) : "f"(a3), "f"(a3));
                asm("fma.rn.f32x2 %0, %1, %2, %0;" : "+l"(acc[3][0]) : "l"(av), "l"(bx));
                asm("fma.rn.f32x2 %0, %1, %2, %0;" : "+l"(acc[3][1]) : "l"(av), "l"(by));
            }
            __syncthreads();
            if (more) {
#pragma unroll
                for (int r = 0; r < 2; r++) {
                    int idx = tid + r * 256;
                    int kk = idx >> 4, nq = idx & 15;
                    *(float4*)(w1S + (buf ^ 1) * 32 * WSTR + kk * WSTR + nq * 4) = pre[r];
                }
            }
            __syncthreads();
            buf ^= 1;
        }

        // Epilogue for this N-chunk: bias + tanh + V-dot
#pragma unroll
        for (int i = 0; i < 4; i++) {
#pragma unroll
            for (int jp = 0; jp < 2; jp++) {
                float hx, hy;
                asm("mov.b64 {%0, %1}, %2;" : "=f"(hx), "=f"(hy) : "l"(acc[i][jp]));
                int u0 = nc * 64 + tx * 4 + jp * 2;
                float t0 = tanh_fast(hx + gB[u0]);
                float t1 = tanh_fast(hy + gB[u0 + 1]);
                scp[i] = fmaf(t0, Vs[u0], fmaf(t1, Vs[u0 + 1], scp[i]));
            }
        }
    }

    // Reduce partial scores across the 16 tx lanes (stays within 16-lane groups)
#pragma unroll
    for (int i = 0; i < 4; i++) {
#pragma unroll
        for (int off = 8; off > 0; off >>= 1)
            scp[i] += __shfl_xor_sync(0xffffffffu, scp[i], off);
    }
    if (tx == 0) {
#pragma unroll
        for (int i = 0; i < 4; i++)
            g_scores[b * SS + s0 + ty * 4 + i] = scp[i] + bv0;
    }
}

// ---------------------------------------------------------------------------
// Kernel C: softmax over S per batch; write attn to d_out; zero context region
// ---------------------------------------------------------------------------
__global__ __launch_bounds__(256) void kernC(float* __restrict__ out) {
    __shared__ float red[256];
    int b = blockIdx.x, tid = threadIdx.x;
    float v[8];
    float mx = -1e30f;
#pragma unroll
    for (int j = 0; j < 8; j++) {
        v[j] = g_scores[b * SS + tid + j * 256];
        mx = fmaxf(mx, v[j]);
    }
    red[tid] = mx;
    __syncthreads();
    for (int o = 128; o > 0; o >>= 1) {
        if (tid < o) red[tid] = fmaxf(red[tid], red[tid + o]);
        __syncthreads();
    }
    mx = red[0];
    __syncthreads();
    float s = 0.0f;
#pragma unroll
    for (int j = 0; j < 8; j++) {
        v[j] = __expf(v[j] - mx);
        s += v[j];
    }
    red[tid] = s;
    __syncthreads();
    for (int o = 128; o > 0; o >>= 1) {
        if (tid < o) red[tid] += red[tid + o];
        __syncthreads();
    }
    float inv = 1.0f / red[0];
#pragma unroll
    for (int j = 0; j < 8; j++)
        out[BB * UU + b * SS + tid + j * 256] = v[j] * inv;
    // zero context region for kernD atomics (d_out is poisoned)
    for (int i = tid; i < 512; i += 256) out[b * 512 + i] = 0.0f;
}

// ---------------------------------------------------------------------------
// Kernel D: context[b,d] = sum_s attn[b,s] * enc[b,s,d]; split over 16 s-chunks
// ---------------------------------------------------------------------------
__global__ __launch_bounds__(512) void kernD(const float* __restrict__ enc,
                                             float* __restrict__ out) {
    __shared__ float as[128];
    int b = blockIdx.y, c = blockIdx.x, tid = threadIdx.x;
    if (tid < 128) as[tid] = out[BB * UU + b * SS + c * 128 + tid];
    __syncthreads();
    const float* e = enc + ((size_t)(b * SS + c * 128)) * DD + tid;
    float acc = 0.0f;
#pragma unroll 8
    for (int i = 0; i < 128; i++) acc = fmaf(as[i], e[(size_t)i * DD], acc);
    atomicAdd(&out[b * 512 + tid], acc);
}

// ---------------------------------------------------------------------------
extern "C" void kernel_launch(void* const* d_in, const int* in_sizes, int n_in,
                              void* d_out, int out_size) {
    const float* enc = (const float*)d_in[0];
    const float* dec = (const float*)d_in[1];
    const float* W1  = (const float*)d_in[2];
    const float* b1  = (const float*)d_in[3];
    const float* W2  = (const float*)d_in[4];
    const float* b2  = (const float*)d_in[5];
    const float* V   = (const float*)d_in[6];
    const float* bv  = (const float*)d_in[7];
    float* out = (float*)d_out;

    size_t smemB = SMEM_FLOATS * sizeof(float);  // ~150 KB
    cudaFuncSetAttribute(kernB, cudaFuncAttributeMaxDynamicSharedMemorySize,
                         (int)smemB);

    kernA<<<BB, 512>>>(dec, W2, b1, b2);
    kernB<<<(BB * SS) / 64, 256, smemB>>>(enc, W1, V, bv);
    kernC<<<BB, 256>>>(out);
    kernD<<<dim3(16, BB), 512>>>(enc, out);
}

// round 3
// speedup vs baseline: 2.7092x; 2.7092x over previous
#include <cuda_runtime.h>
#include <cuda_bf16.h>
#include <cstdint>

#define BB 64
#define SS 2048
#define DD 512
#define UU 512

// ---------------- scratch globals (no allocations allowed) ------------------
__device__ float g_bias[BB * UU];                  // dec@W2 + b1 + b2
__device__ float g_scores[BB * SS];                // pre-softmax scores
// enc converted: row r -> [hi k0..511 | lo k0..511] bf16  (256 MB)
__device__ __nv_bfloat16 g_encA[(size_t)BB * SS * 1024];
// W1 converted to [u][ hi k0..511 | lo k0..511 ]  (1 MB)
__device__ __nv_bfloat16 g_W1img[(size_t)UU * 1024];

// ---------------- helpers ----------------------------------------------------
__device__ __forceinline__ float tanh_fast(float x) {
    float e = __expf(2.0f * x);
    return 1.0f - __fdividef(2.0f, e + 1.0f);
}
__device__ __forceinline__ uint32_t smem_u32(const void* p) {
    uint32_t a;
    asm("{ .reg .u64 t; cvta.to.shared.u64 t, %1; cvt.u32.u64 %0, t; }"
        : "=r"(a) : "l"(p));
    return a;
}
__device__ __forceinline__ uint32_t pack2(__nv_bfloat16 a, __nv_bfloat16 b) {
    return ((uint32_t)__bfloat16_as_ushort(b) << 16) | __bfloat16_as_ushort(a);
}
#define CP16(dst, src) \
    asm volatile("cp.async.cg.shared.global [%0], [%1], 16;" \
                 :: "r"(dst), "l"(src) : "memory")

// ---------------------------------------------------------------------------
// kernE: enc fp32 -> bf16 hi/lo image
// ---------------------------------------------------------------------------
__global__ __launch_bounds__(256) void kernE(const float* __restrict__ enc) {
    size_t lin = (size_t)blockIdx.x * 256 + threadIdx.x;  // 16.7M threads
    size_t row = lin >> 7;
    int q = (int)(lin & 127);
    float4 f = *(const float4*)(enc + row * DD + q * 4);
    __nv_bfloat16 h0 = __float2bfloat16_rn(f.x), h1 = __float2bfloat16_rn(f.y);
    __nv_bfloat16 h2 = __float2bfloat16_rn(f.z), h3 = __float2bfloat16_rn(f.w);
    __nv_bfloat16 l0 = __float2bfloat16_rn(f.x - __bfloat162float(h0));
    __nv_bfloat16 l1 = __float2bfloat16_rn(f.y - __bfloat162float(h1));
    __nv_bfloat16 l2 = __float2bfloat16_rn(f.z - __bfloat162float(h2));
    __nv_bfloat16 l3 = __float2bfloat16_rn(f.w - __bfloat162float(h3));
    uint2 hv = {pack2(h0, h1), pack2(h2, h3)};
    uint2 lv = {pack2(l0, l1), pack2(l2, l3)};
    *(uint2*)(&g_encA[row * 1024 + q * 4]) = hv;
    *(uint2*)(&g_encA[row * 1024 + 512 + q * 4]) = lv;
}

// ---------------------------------------------------------------------------
// kernW: W1[k][u] -> g_W1img[u][hi k | lo k]; also zero g_scores
// ---------------------------------------------------------------------------
__global__ __launch_bounds__(256) void kernW(const float* __restrict__ W1) {
    int idx = blockIdx.x * 256 + threadIdx.x;  // 0..262143
    int u = idx & 511, kg = idx >> 9;
    float x = W1[(size_t)kg * UU + u];
    __nv_bfloat16 h = __float2bfloat16_rn(x);
    __nv_bfloat16 l = __float2bfloat16_rn(x - __bfloat162float(h));
    g_W1img[(size_t)u * 1024 + kg] = h;
    g_W1img[(size_t)u * 1024 + 512 + kg] = l;
    if (idx < BB * SS) g_scores[idx] = 0.0f;
}

// ---------------------------------------------------------------------------
// kernA: g_bias[b,u] = dec@W2 + b1 + b2
// ---------------------------------------------------------------------------
__global__ __launch_bounds__(512) void kernA(const float* __restrict__ dec,
                                             const float* __restrict__ W2,
                                             const float* __restrict__ b1,
                                             const float* __restrict__ b2) {
    __shared__ float ds[DD];
    int b = blockIdx.x;
    for (int i = threadIdx.x; i < DD; i += blockDim.x) ds[i] = dec[b * DD + i];
    __syncthreads();
    int u = threadIdx.x;
    float acc = 0.0f;
#pragma unroll 8
    for (int k = 0; k < DD; k++) acc = fmaf(ds[k], W2[k * UU + u], acc);
    g_bias[b * UU + u] = acc + b1[u] + b2[u];
}

// ---------------------------------------------------------------------------
// kernB: bf16 mma.sync GEMM (M=128 x N=256 per CTA, K'=1536 = 3 passes x 512)
// fused with bias + tanh + V-dot -> atomicAdd into g_scores.
// ---------------------------------------------------------------------------
#define A_BUF 18432            // 128 rows * 144 B
#define B_OFF 36864            // 2 A bufs
#define B_BUF 36864            // 256 rows * 144 B
#define EXTRA 110592           // 2 B bufs after A bufs
#define SMEM_B_TOTAL (EXTRA + 1024 + 1024 + 2048)

__global__ __launch_bounds__(256, 1) void kernB(const float* __restrict__ Vp) {
    extern __shared__ char smraw[];
    const uint32_t smem = smem_u32(smraw);
    float* gBs = (float*)(smraw + EXTRA);
    float* Vs = (float*)(smraw + EXTRA + 1024);
    float* sPart = (float*)(smraw + EXTRA + 2048);

    const int tid = threadIdx.x;
    const int lane = tid & 31, w = tid >> 5;
    const int wm = w & 1, wn = w >> 1;
    const int R = blockIdx.x * 128;
    const int b = blockIdx.x >> 4;
    const int s0 = (blockIdx.x & 15) * 128;
    const int N0 = blockIdx.y * 256;

    for (int i = tid; i < 256; i += 256) {
        gBs[i] = g_bias[b * 512 + N0 + i];
        Vs[i] = Vp[N0 + i];
    }

    // ---- cp.async tile loader (iteration it: pass p = it/8, k0 = (it%8)*64)
    auto issue_tile = [&](int it, int buf) {
        int p = it >> 3;
        int k0 = (it & 7) * 64;
        uint32_t aPart = (p < 2) ? 0u : 1024u;      // bytes into row
        uint32_t bPart = (p == 1) ? 1024u : 0u;
        const char* aSrc = (const char*)g_encA + (size_t)R * 2048 + aPart + k0 * 2;
        const char* bSrc = (const char*)g_W1img + (size_t)N0 * 2048 + bPart + k0 * 2;
        uint32_t aDst = smem + buf * A_BUF;
        uint32_t bDst = smem + B_OFF + buf * B_BUF;
#pragma unroll
        for (int i = 0; i < 4; i++) {
            int lin = tid + i * 256;
            int row = lin >> 3, c = lin & 7;
            CP16(aDst + row * 144 + c * 16, aSrc + (size_t)row * 2048 + c * 16);
        }
#pragma unroll
        for (int i = 0; i < 8; i++) {
            int lin = tid + i * 256;
            int row = lin >> 3, c = lin & 7;
            CP16(bDst + row * 144 + c * 16, bSrc + (size_t)row * 2048 + c * 16);
        }
        asm volatile("cp.async.commit_group;" ::: "memory");
    };

    float acc[4][8][4];
#pragma unroll
    for (int mt = 0; mt < 4; mt++)
#pragma unroll
        for (int nt = 0; nt < 8; nt++)
#pragma unroll
            for (int j = 0; j < 4; j++) acc[mt][nt][j] = 0.0f;

    issue_tile(0, 0);

    // ldmatrix lane address components (constant across iterations)
    const uint32_t aRowOff =
        (uint32_t)((wm * 64 + (lane & 15)) * 144 + ((lane >> 4) & 1) * 16);
    const uint32_t bRowOff =
        (uint32_t)((wn * 64 + (lane & 7)) * 144 + ((lane >> 3) & 1) * 16);

    for (int it = 0; it < 24; it++) {
        const int buf = it & 1;
        if (it < 23) issue_tile(it + 1, buf ^ 1);
        if (it < 23)
            asm volatile("cp.async.wait_group 1;" ::: "memory");
        else
            asm volatile("cp.async.wait_group 0;" ::: "memory");
        __syncthreads();

        const uint32_t sA = smem + buf * A_BUF + aRowOff;
        const uint32_t sB = smem + B_OFF + buf * B_BUF + bRowOff;
#pragma unroll
        for (int ks = 0; ks < 4; ks++) {
            uint32_t a[4][4];
#pragma unroll
            for (int mt = 0; mt < 4; mt++) {
                asm volatile(
                    "ldmatrix.sync.aligned.m8n8.x4.shared.b16 {%0,%1,%2,%3}, [%4];"
                    : "=r"(a[mt][0]), "=r"(a[mt][1]), "=r"(a[mt][2]), "=r"(a[mt][3])
                    : "r"(sA + mt * 16 * 144 + ks * 32));
            }
            uint32_t bf[8][2];
#pragma unroll
            for (int nt = 0; nt < 8; nt++) {
                asm volatile(
                    "ldmatrix.sync.aligned.m8n8.x2.shared.b16 {%0,%1}, [%2];"
                    : "=r"(bf[nt][0]), "=r"(bf[nt][1])
                    : "r"(sB + nt * 8 * 144 + ks * 32));
            }
#pragma unroll
            for (int mt = 0; mt < 4; mt++)
#pragma unroll
                for (int nt = 0; nt < 8; nt++) {
                    asm volatile(
                        "mma.sync.aligned.m16n8k16.row.col.f32.bf16.bf16.f32 "
                        "{%0,%1,%2,%3}, {%4,%5,%6,%7}, {%8,%9}, {%0,%1,%2,%3};"
                        : "+f"(acc[mt][nt][0]), "+f"(acc[mt][nt][1]),
                          "+f"(acc[mt][nt][2]), "+f"(acc[mt][nt][3])
                        : "r"(a[mt][0]), "r"(a[mt][1]), "r"(a[mt][2]), "r"(a[mt][3]),
                          "r"(bf[nt][0]), "r"(bf[nt][1]));
                }
        }
        __syncthreads();
    }

    // ---- epilogue: bias + tanh + V-dot, reduce to per-row partials ----
    const int t4 = lane & 3;
    float part[4][2];
#pragma unroll
    for (int mt = 0; mt < 4; mt++) { part[mt][0] = 0.f; part[mt][1] = 0.f; }
#pragma unroll
    for (int mt = 0; mt < 4; mt++)
#pragma unroll
        for (int nt = 0; nt < 8; nt++) {
            int n0 = wn * 64 + nt * 8 + 2 * t4;
            float v0 = Vs[n0], v1 = Vs[n0 + 1];
            float g0 = gBs[n0], g1 = gBs[n0 + 1];
            part[mt][0] += tanh_fast(acc[mt][nt][0] + g0) * v0 +
                           tanh_fast(acc[mt][nt][1] + g1) * v1;
            part[mt][1] += tanh_fast(acc[mt][nt][2] + g0) * v0 +
                           tanh_fast(acc[mt][nt][3] + g1) * v1;
        }
#pragma unroll
    for (int mt = 0; mt < 4; mt++)
#pragma unroll
        for (int rr = 0; rr < 2; rr++) {
            part[mt][rr] += __shfl_xor_sync(0xffffffffu, part[mt][rr], 1);
            part[mt][rr] += __shfl_xor_sync(0xffffffffu, part[mt][rr], 2);
        }
    if (t4 == 0) {
        int g = lane >> 2;
#pragma unroll
        for (int mt = 0; mt < 4; mt++)
#pragma unroll
            for (int rr = 0; rr < 2; rr++) {
                int row = wm * 64 + mt * 16 + rr * 8 + g;
                sPart[row * 4 + wn] = part[mt][rr];
            }
    }
    __syncthreads();
    if (tid < 128) {
        float s = sPart[tid * 4] + sPart[tid * 4 + 1] + sPart[tid * 4 + 2] +
                  sPart[tid * 4 + 3];
        atomicAdd(&g_scores[b * SS + s0 + tid], s);
    }
}

// ---------------------------------------------------------------------------
// kernC: softmax over S; writes attn; zeroes context region (bv dropped:
// softmax is shift-invariant)
// ---------------------------------------------------------------------------
__global__ __launch_bounds__(256) void kernC(float* __restrict__ out) {
    __shared__ float red[256];
    int b = blockIdx.x, tid = threadIdx.x;
    float v[8];
    float mx = -1e30f;
#pragma unroll
    for (int j = 0; j < 8; j++) {
        v[j] = g_scores[b * SS + tid + j * 256];
        mx = fmaxf(mx, v[j]);
    }
    red[tid] = mx;
    __syncthreads();
    for (int o = 128; o > 0; o >>= 1) {
        if (tid < o) red[tid] = fmaxf(red[tid], red[tid + o]);
        __syncthreads();
    }
    mx = red[0];
    __syncthreads();
    float s = 0.0f;
#pragma unroll
    for (int j = 0; j < 8; j++) {
        v[j] = __expf(v[j] - mx);
        s += v[j];
    }
    red[tid] = s;
    __syncthreads();
    for (int o = 128; o > 0; o >>= 1) {
        if (tid < o) red[tid] += red[tid + o];
        __syncthreads();
    }
    float inv = 1.0f / red[0];
#pragma unroll
    for (int j = 0; j < 8; j++)
        out[BB * UU + b * SS + tid + j * 256] = v[j] * inv;
    for (int i = tid; i < 512; i += 256) out[b * 512 + i] = 0.0f;
}

// ---------------------------------------------------------------------------
// kernD: context[b,d] = sum_s attn[b,s] * enc[b,s,d]
// ---------------------------------------------------------------------------
__global__ __launch_bounds__(512) void kernD(const float* __restrict__ enc,
                                             float* __restrict__ out) {
    __shared__ float as[128];
    int b = blockIdx.y, c = blockIdx.x, tid = threadIdx.x;
    if (tid < 128) as[tid] = out[BB * UU + b * SS + c * 128 + tid];
    __syncthreads();
    const float* e = enc + ((size_t)(b * SS + c * 128)) * DD + tid;
    float acc = 0.0f;
#pragma unroll 8
    for (int i = 0; i < 128; i++) acc = fmaf(as[i], e[(size_t)i * DD], acc);
    atomicAdd(&out[b * 512 + tid], acc);
}

// ---------------------------------------------------------------------------
extern "C" void kernel_launch(void* const* d_in, const int* in_sizes, int n_in,
                              void* d_out, int out_size) {
    const float* enc = (const float*)d_in[0];
    const float* dec = (const float*)d_in[1];
    const float* W1  = (const float*)d_in[2];
    const float* b1  = (const float*)d_in[3];
    const float* W2  = (const float*)d_in[4];
    const float* b2  = (const float*)d_in[5];
    const float* V   = (const float*)d_in[6];
    float* out = (float*)d_out;

    cudaFuncSetAttribute(kernB, cudaFuncAttributeMaxDynamicSharedMemorySize,
                         SMEM_B_TOTAL);

    kernE<<<65536, 256>>>(enc);
    kernW<<<1024, 256>>>(W1);
    kernA<<<BB, 512>>>(dec, W2, b1, b2);
    kernB<<<dim3(1024, 2), 256, SMEM_B_TOTAL>>>(V);
    kernC<<<BB, 256>>>(out);
    kernD<<<dim3(16, BB), 512>>>(enc, out);
}